// round 4
// baseline (speedup 1.0000x reference)
#include <cuda_runtime.h>
#include <math.h>

#define SS 512   // seq len
#define BB 64    // batch
#define HH 512   // hidden
#define II 512   // input
#define NC 64    // CTAs per direction in recurrent kernel

// ---------------- device scratch (no allocs allowed) ----------------
// xw[dir][s][gate][b][h]  : 2*512*4*64*512 floats = 512 MB
__device__ float g_xw[2][SS][4][BB][HH];
// h double buffer per direction, c single buffer
__device__ float g_h[2][2][BB][HH];
__device__ float g_c[2][BB][HH];
// software grid barrier state per direction
__device__ unsigned int g_cnt[2];
__device__ volatile unsigned int g_rel[2];

// ---------------- init: reset barrier state every launch ----------------
__global__ void init_kernel() {
    g_cnt[0] = 0; g_cnt[1] = 0;
    g_rel[0] = 0; g_rel[1] = 0;
}

// ---------------- phase 1: input projection GEMM ----------------
// For z = dir*4+g : xw[dir][s][g][b][h] = sum_k x[b][s][k] * W[dir][g][k][h] + bias[dir][g][h]
// A = x viewed [B*S, I] (row m = b*S + s), Bmat = W[g] [I, H], tile 64x64x32, 256 thr, 4x4/thread.
__global__ __launch_bounds__(256) void proj_kernel(
    const float* __restrict__ x,
    const float* __restrict__ Wf, const float* __restrict__ bf,
    const float* __restrict__ Wb, const float* __restrict__ bb)
{
    const int z = blockIdx.z;
    const int d = z >> 2, g = z & 3;
    const float* W    = (d ? Wb : Wf) + (size_t)g * II * HH;
    const float* bias = (d ? bb : bf) + g * HH;
    const int m0 = blockIdx.x * 64;
    const int n0 = blockIdx.y * 64;

    __shared__ float As[32][68];   // [k][m], padded
    __shared__ float Bs[32][64];   // [k][n]

    const int tid = threadIdx.x;
    const int mg = tid & 15, ng = tid >> 4;

    float acc[4][4] = {};

    for (int kc = 0; kc < II; kc += 32) {
        __syncthreads();
        // A tile: 64 rows x 32 k, transposed into As
        #pragma unroll
        for (int w = 0; w < 2; w++) {
            int f4 = tid + w * 256;
            int row = f4 >> 3;
            int k4 = (f4 & 7) << 2;
            float4 v = *(const float4*)&x[(size_t)(m0 + row) * II + kc + k4];
            As[k4 + 0][row] = v.x; As[k4 + 1][row] = v.y;
            As[k4 + 2][row] = v.z; As[k4 + 3][row] = v.w;
        }
        // B tile: 32 k rows x 64 n
        #pragma unroll
        for (int w = 0; w < 2; w++) {
            int f4 = tid + w * 256;
            int row = f4 >> 4;
            int c4 = (f4 & 15) << 2;
            *(float4*)&Bs[row][c4] = *(const float4*)&W[(size_t)(kc + row) * HH + n0 + c4];
        }
        __syncthreads();
        #pragma unroll
        for (int k = 0; k < 32; k++) {
            float4 a = *(float4*)&As[k][mg << 2];
            float4 bv = *(float4*)&Bs[k][ng << 2];
            float av[4] = {a.x, a.y, a.z, a.w};
            float bb2[4] = {bv.x, bv.y, bv.z, bv.w};
            #pragma unroll
            for (int i = 0; i < 4; i++)
                #pragma unroll
                for (int j = 0; j < 4; j++)
                    acc[i][j] += av[i] * bb2[j];
        }
    }

    #pragma unroll
    for (int i = 0; i < 4; i++) {
        int m = m0 + (mg << 2) + i;
        int b = m >> 9;          // m = b*512 + s  (S = 512)
        int s = m & 511;
        #pragma unroll
        for (int j = 0; j < 4; j++) {
            int n = n0 + (ng << 2) + j;
            g_xw[d][s][g][b][n] = acc[i][j] + bias[n];
        }
    }
}

// ---------------- per-direction grid barrier ----------------
// Arrive via one gmem atomic per CTA; release via volatile store; spin on
// volatile load (no atomic-ALU contention), with nanosleep backoff.
__device__ __forceinline__ void grid_barrier(int dir, unsigned int gen) {
    __syncthreads();
    if (threadIdx.x == 0) {
        __threadfence();
        unsigned int n = atomicAdd(&g_cnt[dir], 1u);
        if (n == NC - 1) {
            g_cnt[dir] = 0;
            __threadfence();
            g_rel[dir] = gen;
        } else {
            while (g_rel[dir] < gen) { __nanosleep(128); }
            __threadfence();
        }
    }
    __syncthreads();
}

// ---------------- phase 2: persistent recurrent kernel ----------------
// grid = 128 CTAs: blockIdx.x/64 = dir, %64 = h-slice of 8 columns.
// 128 threads: tid%8 = local h-col j, tid/8 = r -> batches r*4..r*4+3.
// Each thread accumulates [4 batches][4 gates] for ONE h column => pointwise is thread-local.
__global__ void __launch_bounds__(128, 1) lstm_kernel(
    const float* __restrict__ Uf, const float* __restrict__ Ub,
    float* __restrict__ out)
{
    const int dir = blockIdx.x >> 6;
    const int slice = blockIdx.x & 63;
    const int h0 = slice * 8;

    extern __shared__ float sm[];
    float* Us = sm;                 // [32 cols][516]  col = g*8 + j, indexed by global k
    float* hs = sm + 32 * 516;      // [64][68]

    const int tid = threadIdx.x;
    const int j = tid & 7;
    const int r = tid >> 3;
    const int b0 = r << 2;

    const float* U = dir ? Ub : Uf;   // [4][HH][HH]

    // Load U slice into smem: Us[c][k] = U[g][k][h0 + (c&7)], c = g*8 + (c&7)
    for (int idx = tid; idx < 32 * 512; idx += 128) {
        int c = idx & 31;
        int k = idx >> 5;
        Us[c * 516 + k] = U[((size_t)(c >> 3) * HH + k) * HH + h0 + (c & 7)];
    }

    // Zero h buffer 0 and c for this slice
    for (int idx = tid; idx < 512; idx += 128) {
        int b = idx >> 3, jj = idx & 7;
        g_h[dir][0][b][h0 + jj] = 0.0f;
        g_c[dir][b][h0 + jj] = 0.0f;
    }

    grid_barrier(dir, 1u);

    for (int t = 0; t < SS; t++) {
        const int s = dir ? (SS - 1 - t) : t;

        // Prefetch xw slice for this step into registers (hides latency under GEMM)
        const float* xwp = &g_xw[dir][s][0][0][0];
        float xr[4][4];
        #pragma unroll
        for (int g = 0; g < 4; g++)
            #pragma unroll
            for (int i = 0; i < 4; i++)
                xr[i][g] = xwp[((g << 6) + b0 + i) * HH + h0 + j];

        const float* hprev = &g_h[dir][t & 1][0][0];
        float acc[4][4] = {};   // [batch][gate]

        #pragma unroll 1
        for (int kc = 0; kc < HH; kc += 64) {
            __syncthreads();
            #pragma unroll
            for (int w = 0; w < 8; w++) {
                int f4 = tid + w * 128;
                int row = f4 >> 4;
                int c4 = (f4 & 15) << 2;
                *(float4*)&hs[row * 68 + c4] = *(const float4*)&hprev[row * HH + kc + c4];
            }
            __syncthreads();
            #pragma unroll
            for (int k = 0; k < 64; k += 4) {
                float4 hv[4], uv[4];
                #pragma unroll
                for (int i = 0; i < 4; i++)
                    hv[i] = *(float4*)&hs[(b0 + i) * 68 + k];
                #pragma unroll
                for (int g = 0; g < 4; g++)
                    uv[g] = *(float4*)&Us[((g << 3) + j) * 516 + kc + k];
                #pragma unroll
                for (int i = 0; i < 4; i++)
                    #pragma unroll
                    for (int g = 0; g < 4; g++) {
                        acc[i][g] += hv[i].x * uv[g].x;
                        acc[i][g] += hv[i].y * uv[g].y;
                        acc[i][g] += hv[i].z * uv[g].z;
                        acc[i][g] += hv[i].w * uv[g].w;
                    }
            }
        }

        // Pointwise LSTM cell (gate order f, g, i, o) + writes
        float* hnext = &g_h[dir][(t + 1) & 1][0][0];
        const int hc = h0 + j;
        #pragma unroll
        for (int i = 0; i < 4; i++) {
            const int b = b0 + i;
            float pf = acc[i][0] + xr[i][0];
            float pg = acc[i][1] + xr[i][1];
            float pi = acc[i][2] + xr[i][2];
            float po = acc[i][3] + xr[i][3];
            float fg = 1.0f / (1.0f + __expf(-pf));
            float gg = tanhf(pg);
            float ig = 1.0f / (1.0f + __expf(-pi));
            float og = 1.0f / (1.0f + __expf(-po));
            float cnew = g_c[dir][b][hc] * fg + gg * ig;
            g_c[dir][b][hc] = cnew;
            float hn = og * tanhf(cnew);
            hnext[b * HH + hc] = hn;
            out[(size_t)((s << 6) + b) * 1024 + dir * HH + hc] = hn;
        }

        grid_barrier(dir, (unsigned)(t + 2));
    }
}

// ---------------- phase 3: finalize h_f / h_b from mask ----------------
__global__ void final_kernel(const unsigned char* __restrict__ mask,
                             float* __restrict__ out)
{
    const int b = blockIdx.x;
    const int tid = threadIdx.x;

    __shared__ int mode;  // 1 if mask stored as int32, 0 if uint8
    if (tid == 0)
        mode = (mask[0] == 1 && mask[1] == 0 && mask[2] == 0 && mask[3] == 0) ? 1 : 0;
    __syncthreads();

    int v;
    if (mode) {
        const int* mi = (const int*)mask;
        v = (mi[b * SS + tid] != 0) ? 1 : 0;
    } else {
        v = (mask[b * SS + tid] != 0) ? 1 : 0;
    }
    int len = __syncthreads_count(v);
    int idx = (len > 0) ? (len - 1) : 0;

    float* hf = out + (size_t)SS * BB * 1024;
    float* hb = hf + (size_t)BB * HH;
    hf[b * HH + tid] = out[(size_t)((idx << 6) + b) * 1024 + tid];
    hb[b * HH + tid] = out[(size_t)b * 1024 + HH + tid];
}

// ---------------- launch ----------------
extern "C" void kernel_launch(void* const* d_in, const int* in_sizes, int n_in,
                              void* d_out, int out_size)
{
    const float* x  = (const float*)d_in[0];
    const unsigned char* mask = (const unsigned char*)d_in[1];
    const float* Uf = (const float*)d_in[2];
    const float* Wf = (const float*)d_in[3];
    const float* bf = (const float*)d_in[4];
    const float* Ub = (const float*)d_in[5];
    const float* Wb = (const float*)d_in[6];
    const float* bb = (const float*)d_in[7];
    float* out = (float*)d_out;

    init_kernel<<<1, 32>>>();

    dim3 pg(512, 8, 8);   // (M/64, H/64, dir*4+gate)
    proj_kernel<<<pg, 256>>>(x, Wf, bf, Wb, bb);

    size_t smem = (size_t)(32 * 516 + 64 * 68) * sizeof(float);  // ~83.5 KB
    cudaFuncSetAttribute(lstm_kernel, cudaFuncAttributeMaxDynamicSharedMemorySize, (int)smem);
    lstm_kernel<<<128, 128, smem>>>(Uf, Ub, out);

    final_kernel<<<BB, SS>>>(mask, out);
}

// round 5
// speedup vs baseline: 2.8269x; 2.8269x over previous
#include <cuda_runtime.h>
#include <cuda_fp16.h>
#include <math.h>

#define SS 512   // seq len
#define BB 64    // batch
#define HH 512   // hidden
#define II 512   // input
#define NC 64    // CTAs per direction in recurrent kernel

// ---------------- device scratch (no allocs allowed) ----------------
// xw[d*4+g][m][h], m = b*512 + s   : 512 MB fp32
__device__ float g_xw[8][BB * SS][HH];
// fp16 h double buffer per direction
__device__ __half g_h16[2][2][BB][HH];
// software grid barrier state per direction
__device__ unsigned int g_cnt[2];
__device__ volatile unsigned int g_rel[2];

// ---------------- PTX helpers ----------------
__device__ __forceinline__ void mma16816(float* c, const unsigned* a, const unsigned* b) {
    asm volatile(
        "mma.sync.aligned.m16n8k16.row.col.f32.f16.f16.f32 "
        "{%0,%1,%2,%3}, {%4,%5,%6,%7}, {%8,%9}, {%0,%1,%2,%3};\n"
        : "+f"(c[0]), "+f"(c[1]), "+f"(c[2]), "+f"(c[3])
        : "r"(a[0]), "r"(a[1]), "r"(a[2]), "r"(a[3]), "r"(b[0]), "r"(b[1]));
}

__device__ __forceinline__ void ldmx4(unsigned* a, const void* p) {
    unsigned addr = (unsigned)__cvta_generic_to_shared(p);
    asm volatile("ldmatrix.sync.aligned.m8n8.x4.shared.b16 {%0,%1,%2,%3}, [%4];"
                 : "=r"(a[0]), "=r"(a[1]), "=r"(a[2]), "=r"(a[3]) : "r"(addr));
}

__device__ __forceinline__ void cpa16(void* s, const void* g) {
    unsigned sa = (unsigned)__cvta_generic_to_shared(s);
    asm volatile("cp.async.cg.shared.global [%0], [%1], 16;" :: "r"(sa), "l"(g));
}
#define CP_COMMIT() asm volatile("cp.async.commit_group;")
#define CP_WAIT(n)  asm volatile("cp.async.wait_group %0;" :: "n"(n))

// ---------------- init: reset barrier state every launch ----------------
__global__ void init_kernel() {
    g_cnt[0] = 0; g_cnt[1] = 0;
    g_rel[0] = 0; g_rel[1] = 0;
}

// ---------------- phase 1: input projection GEMM (fp16 MMA) ----------------
// z = d*4+g : xw[z][m][h] = sum_k x[m][k]*W[k][h] + bias[h],  m = b*512+s
// CTA tile 128(M) x 64(N), K-chunk 64, 256 threads = 8 warps (4m x 2n), warp tile 32x32.
__global__ __launch_bounds__(256) void proj_kernel(
    const float* __restrict__ x,
    const float* __restrict__ Wf, const float* __restrict__ bf,
    const float* __restrict__ Wb, const float* __restrict__ bb)
{
    const int z = blockIdx.z;
    const int d = z >> 2, g = z & 3;
    const float* W    = (d ? Wb : Wf) + (size_t)g * II * HH;
    const float* bias = (d ? bb : bf) + g * HH;
    const int m0 = blockIdx.x * 128;
    const int n0 = blockIdx.y * 64;

    __shared__ __half As[128 * 72];   // [m][k] rows of 64 (+8 pad)
    __shared__ __half Bs[64 * 72];    // [n][k]

    const int tid  = threadIdx.x;
    const int lane = tid & 31;
    const int wid  = tid >> 5;
    const int wm   = wid & 3;    // m-quarter (32 rows)
    const int wn   = wid >> 2;   // n-half (32 cols)

    const int arow = (lane & 7) | (((lane >> 3) & 1) << 3);
    const int acol = (lane >> 4) << 3;

    float acc[2][4][4];
    #pragma unroll
    for (int i = 0; i < 2; i++)
        #pragma unroll
        for (int jj = 0; jj < 4; jj++)
            #pragma unroll
            for (int q = 0; q < 4; q++) acc[i][jj][q] = 0.f;

    for (int kc = 0; kc < II; kc += 64) {
        __syncthreads();
        // A: x[m0..m0+127][kc..kc+63] -> fp16
        #pragma unroll
        for (int w = 0; w < 8; w++) {
            int f4 = tid + w * 256;
            int row = f4 >> 4, k4 = (f4 & 15) << 2;
            float4 v = *(const float4*)&x[(size_t)(m0 + row) * II + kc + k4];
            *(__half2*)&As[row * 72 + k4]     = __floats2half2_rn(v.x, v.y);
            *(__half2*)&As[row * 72 + k4 + 2] = __floats2half2_rn(v.z, v.w);
        }
        // B: W[kc+k][n0+n] -> Bs[n][k] (transpose)
        #pragma unroll
        for (int w = 0; w < 4; w++) {
            int f4 = tid + w * 256;
            int k = f4 >> 4, n4 = (f4 & 15) << 2;
            float4 v = *(const float4*)&W[(size_t)(kc + k) * HH + n0 + n4];
            Bs[(n4 + 0) * 72 + k] = __float2half_rn(v.x);
            Bs[(n4 + 1) * 72 + k] = __float2half_rn(v.y);
            Bs[(n4 + 2) * 72 + k] = __float2half_rn(v.z);
            Bs[(n4 + 3) * 72 + k] = __float2half_rn(v.w);
        }
        __syncthreads();
        #pragma unroll
        for (int k16 = 0; k16 < 4; k16++) {
            unsigned a[2][4], b[4][2];
            #pragma unroll
            for (int mt = 0; mt < 2; mt++)
                ldmx4(a[mt], &As[(wm * 32 + mt * 16 + arow) * 72 + k16 * 16 + acol]);
            #pragma unroll
            for (int nt = 0; nt < 4; nt++) {
                const __half* bp = &Bs[(wn * 32 + nt * 8 + (lane >> 2)) * 72 + k16 * 16 + ((lane & 3) << 1)];
                b[nt][0] = *(const unsigned*)bp;
                b[nt][1] = *(const unsigned*)(bp + 8);
            }
            #pragma unroll
            for (int mt = 0; mt < 2; mt++)
                #pragma unroll
                for (int nt = 0; nt < 4; nt++)
                    mma16816(acc[mt][nt], a[mt], b[nt]);
        }
    }

    // epilogue: sector-aligned float2 stores + bias
    #pragma unroll
    for (int mt = 0; mt < 2; mt++) {
        #pragma unroll
        for (int nt = 0; nt < 4; nt++) {
            int n = n0 + wn * 32 + nt * 8 + ((lane & 3) << 1);
            float bx = bias[n], by = bias[n + 1];
            int mA = m0 + wm * 32 + mt * 16 + (lane >> 2);
            *(float2*)&g_xw[z][mA][n]     = make_float2(acc[mt][nt][0] + bx, acc[mt][nt][1] + by);
            *(float2*)&g_xw[z][mA + 8][n] = make_float2(acc[mt][nt][2] + bx, acc[mt][nt][3] + by);
        }
    }
}

// ---------------- per-direction grid barrier ----------------
__device__ __forceinline__ void grid_barrier(int dir, unsigned int gen) {
    __syncthreads();
    if (threadIdx.x == 0) {
        __threadfence();
        unsigned int n = atomicAdd(&g_cnt[dir], 1u);
        if (n == NC - 1) {
            g_cnt[dir] = 0;
            __threadfence();
            g_rel[dir] = gen;
        } else {
            while (g_rel[dir] < gen) { __nanosleep(64); }
            __threadfence();
        }
    }
    __syncthreads();
}

// ---------------- phase 2: persistent recurrent kernel (fp16 MMA) ----------------
// 128 CTAs: dir = bid/64, slice = bid%64 -> 8 h-cols. Per step: preact[64b x 32(4g x 8h)]
// = h16[64 x 512] @ U16slice[512 x 32] via m16n8k16. 128 threads = 4 warps (2m x 2n).
__device__ __forceinline__ void issue_chunk(__half* As, const __half* hprev, int ch, int tid) {
    const int kc = ch * 128;
    #pragma unroll
    for (int w = 0; w < 8; w++) {
        int flat = tid + w * 128;          // 1024 x 16B units = 64 rows x 256 B
        int row = flat >> 4;
        int c16 = flat & 15;
        cpa16(&As[row * 520 + kc + c16 * 8], &hprev[row * 512 + kc + c16 * 8]);
    }
    CP_COMMIT();
}

__global__ void __launch_bounds__(128, 1) lstm_kernel(
    const float* __restrict__ Uf, const float* __restrict__ Ub,
    float* __restrict__ out)
{
    const int dir = blockIdx.x >> 6;
    const int slice = blockIdx.x & 63;
    const int h0 = slice * 8;

    extern __shared__ __align__(16) char smraw[];
    __half* As  = (__half*)smraw;            // [64][520]  h tile
    __half* Us  = As + 64 * 520;             // [32][520]  U slice, col = g*8+j
    float*  pre = (float*)(Us + 32 * 520);   // [4][64][10] gate exchange

    const int tid  = threadIdx.x;
    const int lane = tid & 31;
    const int wid  = tid >> 5;
    const int wm   = wid & 1;     // m-half (32 batches)
    const int wn   = wid >> 1;    // n-half (2 gates)
    const int j    = tid & 7;     // pointwise h-col
    const int b0j  = (tid >> 3) * 4;  // pointwise batch base

    const int arow = (lane & 7) | (((lane >> 3) & 1) << 3);
    const int acol = (lane >> 4) << 3;

    const float* U = dir ? Ub : Uf;   // [4][HH][HH]

    // U slice -> fp16 smem
    for (int idx = tid; idx < 32 * 512; idx += 128) {
        int c = idx & 31, k = idx >> 5;
        Us[c * 520 + k] = __float2half_rn(U[((size_t)(c >> 3) * HH + k) * HH + h0 + (c & 7)]);
    }
    // zero h buffer 0 for this slice
    for (int idx = tid; idx < 512; idx += 128) {
        int b = idx >> 3, jj = idx & 7;
        g_h16[dir][0][b][h0 + jj] = __float2half_rn(0.f);
    }

    float creg[4] = {0.f, 0.f, 0.f, 0.f};

    grid_barrier(dir, 1u);

    for (int t = 0; t < SS; t++) {
        const int s = dir ? (SS - 1 - t) : t;
        const __half* hprev = &g_h16[dir][t & 1][0][0];

        issue_chunk(As, hprev, 0, tid);

        // xw prefetch (no dependency on barrier data)
        float xr[4][4];
        #pragma unroll
        for (int g2 = 0; g2 < 4; g2++)
            #pragma unroll
            for (int i = 0; i < 4; i++)
                xr[i][g2] = g_xw[dir * 4 + g2][(size_t)(b0j + i) * 512 + s][h0 + j];

        float acc[2][2][4];
        #pragma unroll
        for (int a1 = 0; a1 < 2; a1++)
            #pragma unroll
            for (int a2 = 0; a2 < 2; a2++)
                #pragma unroll
                for (int q = 0; q < 4; q++) acc[a1][a2][q] = 0.f;

        #pragma unroll
        for (int ch = 0; ch < 4; ch++) {
            if (ch < 3) { issue_chunk(As, hprev, ch + 1, tid); CP_WAIT(1); }
            else        { CP_WAIT(0); }
            __syncthreads();
            const int kc = ch * 128;
            #pragma unroll
            for (int k16 = 0; k16 < 8; k16++) {
                const int k0 = kc + k16 * 16;
                unsigned a[2][4], b[2][2];
                #pragma unroll
                for (int mt = 0; mt < 2; mt++)
                    ldmx4(a[mt], &As[(wm * 32 + mt * 16 + arow) * 520 + k0 + acol]);
                #pragma unroll
                for (int nt = 0; nt < 2; nt++) {
                    const __half* bp = &Us[(wn * 16 + nt * 8 + (lane >> 2)) * 520 + k0 + ((lane & 3) << 1)];
                    b[nt][0] = *(const unsigned*)bp;
                    b[nt][1] = *(const unsigned*)(bp + 8);
                }
                #pragma unroll
                for (int mt = 0; mt < 2; mt++)
                    #pragma unroll
                    for (int nt = 0; nt < 2; nt++)
                        mma16816(acc[mt][nt], a[mt], b[nt]);
            }
        }

        // gate exchange: frags -> pre[gate][b][j]
        #pragma unroll
        for (int mt = 0; mt < 2; mt++) {
            #pragma unroll
            for (int nt = 0; nt < 2; nt++) {
                int gate = wn * 2 + nt;
                int jloc = (lane & 3) << 1;
                int b = wm * 32 + mt * 16 + (lane >> 2);
                *(float2*)&pre[(gate * 64 + b) * 10 + jloc]       = make_float2(acc[mt][nt][0], acc[mt][nt][1]);
                *(float2*)&pre[(gate * 64 + b + 8) * 10 + jloc]   = make_float2(acc[mt][nt][2], acc[mt][nt][3]);
            }
        }
        __syncthreads();

        // pointwise LSTM cell (gate order f,g,i,o); c lives in registers
        __half* hnext = &g_h16[dir][(t + 1) & 1][0][0];
        const int hc = h0 + j;
        #pragma unroll
        for (int i = 0; i < 4; i++) {
            const int b = b0j + i;
            float pf = pre[(0 * 64 + b) * 10 + j] + xr[i][0];
            float pg = pre[(1 * 64 + b) * 10 + j] + xr[i][1];
            float pi = pre[(2 * 64 + b) * 10 + j] + xr[i][2];
            float po = pre[(3 * 64 + b) * 10 + j] + xr[i][3];
            float fg = 1.0f / (1.0f + __expf(-pf));
            float gg = tanhf(pg);
            float ig = 1.0f / (1.0f + __expf(-pi));
            float og = 1.0f / (1.0f + __expf(-po));
            creg[i] = creg[i] * fg + gg * ig;
            float hn = og * tanhf(creg[i]);
            hnext[b * HH + hc] = __float2half_rn(hn);
            out[(size_t)((s << 6) + b) * 1024 + dir * HH + hc] = hn;
        }

        grid_barrier(dir, (unsigned)(t + 2));
    }
}

// ---------------- phase 3: finalize h_f / h_b from mask ----------------
__global__ void final_kernel(const unsigned char* __restrict__ mask,
                             float* __restrict__ out)
{
    const int b = blockIdx.x;
    const int tid = threadIdx.x;

    __shared__ int mode;  // 1 if mask stored as int32, 0 if uint8
    if (tid == 0)
        mode = (mask[0] == 1 && mask[1] == 0 && mask[2] == 0 && mask[3] == 0) ? 1 : 0;
    __syncthreads();

    int v;
    if (mode) {
        const int* mi = (const int*)mask;
        v = (mi[b * SS + tid] != 0) ? 1 : 0;
    } else {
        v = (mask[b * SS + tid] != 0) ? 1 : 0;
    }
    int len = __syncthreads_count(v);
    int idx = (len > 0) ? (len - 1) : 0;

    float* hf = out + (size_t)SS * BB * 1024;
    float* hb = hf + (size_t)BB * HH;
    hf[b * HH + tid] = out[(size_t)((idx << 6) + b) * 1024 + tid];
    hb[b * HH + tid] = out[(size_t)b * 1024 + HH + tid];
}

// ---------------- launch ----------------
extern "C" void kernel_launch(void* const* d_in, const int* in_sizes, int n_in,
                              void* d_out, int out_size)
{
    const float* x  = (const float*)d_in[0];
    const unsigned char* mask = (const unsigned char*)d_in[1];
    const float* Uf = (const float*)d_in[2];
    const float* Wf = (const float*)d_in[3];
    const float* bf = (const float*)d_in[4];
    const float* Ub = (const float*)d_in[5];
    const float* Wb = (const float*)d_in[6];
    const float* bb = (const float*)d_in[7];
    float* out = (float*)d_out;

    init_kernel<<<1, 32>>>();

    dim3 pg(BB * SS / 128, HH / 64, 8);   // (256, 8, 8)
    proj_kernel<<<pg, 256>>>(x, Wf, bf, Wb, bb);

    size_t smem = (size_t)(64 * 520 + 32 * 520) * sizeof(__half)
                + (size_t)(4 * 64 * 10) * sizeof(float);   // 110,080 B
    cudaFuncSetAttribute(lstm_kernel, cudaFuncAttributeMaxDynamicSharedMemorySize, (int)smem);
    lstm_kernel<<<128, 128, smem>>>(Uf, Ub, out);

    final_kernel<<<BB, SS>>>(mask, out);
}